// round 10
// baseline (speedup 1.0000x reference)
#include <cuda_runtime.h>
#include <math.h>

#define N_NODES 50000
#define E_EDGES 800000
#define E_TOT   (E_EDGES + N_NODES)   // 850000 with self loops
#define F_IN    128
#define SLOPE   0.2f

// ---------------- scratch (static __device__ — no allocation) ----------------
__device__ float g_h[N_NODES * 128];        // transformed features (fp32)
__device__ float g_o[N_NODES * 128];        // aggregated output
__device__ float g_als[N_NODES * 4];
__device__ float g_ald[N_NODES * 4];
__device__ int   g_cnt[N_NODES];
__device__ int   g_off[N_NODES + 1];
__device__ int   g_cur[N_NODES];
__device__ int   g_csrc[E_TOT];

// ---------------- CSR build ----------------
__global__ void zero_int_kernel(int* p, int n) {
    int i = blockIdx.x * blockDim.x + threadIdx.x;
    if (i < n) p[i] = 0;
}

__global__ void hist_kernel(const int* __restrict__ ei, int* __restrict__ cnt) {
    int e = blockIdx.x * blockDim.x + threadIdx.x;
    if (e >= E_TOT) return;
    int d = (e < E_EDGES) ? ei[E_EDGES + e] : (e - E_EDGES);
    atomicAdd(&cnt[d], 1);
}

__global__ void scan_kernel(const int* __restrict__ cnt,
                            int* __restrict__ offsets,
                            int* __restrict__ cursor) {
    __shared__ int part[1024];
    const int T = 1024;
    const int C = (N_NODES + T - 1) / T;   // 49
    int t = threadIdx.x;
    int lo = t * C;
    int hi = lo + C; if (hi > N_NODES) hi = N_NODES;
    int s = 0;
    for (int i = lo; i < hi; i++) s += cnt[i];
    part[t] = s;
    __syncthreads();
    for (int off = 1; off < T; off <<= 1) {
        int v = (t >= off) ? part[t - off] : 0;
        __syncthreads();
        part[t] += v;
        __syncthreads();
    }
    int run = (t > 0) ? part[t - 1] : 0;   // exclusive base
    for (int i = lo; i < hi; i++) {
        offsets[i] = run;
        cursor[i]  = run;
        run += cnt[i];
    }
    if (t == 0) offsets[N_NODES] = E_TOT;
}

__global__ void scatter_kernel(const int* __restrict__ ei,
                               int* __restrict__ cursor,
                               int* __restrict__ csr_src) {
    int e = blockIdx.x * blockDim.x + threadIdx.x;
    if (e >= E_TOT) return;
    int s, d;
    if (e < E_EDGES) { s = ei[e]; d = ei[E_EDGES + e]; }
    else             { s = d = e - E_EDGES; }
    int pos = atomicAdd(&cursor[d], 1);
    csr_src[pos] = s;
}

// ---------------- tf32 helpers ----------------
__device__ __forceinline__ float tf32r(float x) {
    float r;
    asm("cvt.rna.tf32.f32 %0, %1;" : "=f"(r) : "f"(x));
    return r;
}

__device__ __forceinline__ void mma_tf32(float& c0, float& c1, float& c2, float& c3,
                                         unsigned a0, unsigned a1, unsigned a2, unsigned a3,
                                         unsigned b0, unsigned b1) {
    asm volatile(
        "mma.sync.aligned.m16n8k8.row.col.f32.tf32.tf32.f32 "
        "{%0,%1,%2,%3}, {%4,%5,%6,%7}, {%8,%9}, {%0,%1,%2,%3};"
        : "+f"(c0), "+f"(c1), "+f"(c2), "+f"(c3)
        : "r"(a0), "r"(a1), "r"(a2), "r"(a3), "r"(b0), "r"(b1));
}

// ---------------- GEMM (tf32x3) + fused attention-coef epilogue ----------------
// Block: 256 threads (8 warps), 128 rows. Warp w -> rows 16w..16w+15, all MO cols.
// W k-slices staged in smem (tf32 hi/lo split done once cooperatively).
// Epilogue computes als/ald per row via lane-quad shfl reduction.
template<int MO, int H>
__global__ void __launch_bounds__(256)
gemm_mma(const float* __restrict__ X,
         const float* __restrict__ W,
         const float* __restrict__ bias,
         const float* __restrict__ a_src,
         const float* __restrict__ a_dst,
         float* __restrict__ Hout,
         float* __restrict__ als,
         float* __restrict__ ald) {
    constexpr int XS = 132;                      // X row stride
    constexpr int WS = MO + 8;                   // WS % 32 == 8
    constexpr int NT = MO / 8;                   // n-tiles per warp

    extern __shared__ float smem_f[];
    float* Xs  = smem_f;                         // 128 * XS
    float* Whi = Xs + 128 * XS;                  // 8 * WS
    float* Wlo = Whi + 8 * WS;                   // 8 * WS

    const int tid  = threadIdx.x;
    const int wid  = tid >> 5;
    const int lane = tid & 31;
    const int gp   = lane >> 2;                  // group 0..7
    const int t4   = lane & 3;                   // 0..3
    const int row0 = blockIdx.x * 128;

    // ---- stage X tile (with fused relu(x+bias) of previous layer) ----
#pragma unroll
    for (int it = 0; it < 16; it++) {
        int idx = tid + it * 256;                // 0..4095
        int r  = idx >> 5;
        int k4 = idx & 31;
        int n  = row0 + r;
        float4 v = make_float4(0.f, 0.f, 0.f, 0.f);
        if (n < N_NODES) {
            v = reinterpret_cast<const float4*>(X)[n * 32 + k4];
            if (bias) {
                float4 b = reinterpret_cast<const float4*>(bias)[k4];
                v.x = fmaxf(v.x + b.x, 0.f);
                v.y = fmaxf(v.y + b.y, 0.f);
                v.z = fmaxf(v.z + b.z, 0.f);
                v.w = fmaxf(v.w + b.w, 0.f);
            }
        }
        *reinterpret_cast<float4*>(&Xs[r * XS + 4 * k4]) = v;
    }

    float c[NT][4];
#pragma unroll
    for (int nt = 0; nt < NT; nt++)
#pragma unroll
        for (int j = 0; j < 4; j++) c[nt][j] = 0.f;

    const int ra = wid * 16 + gp;                // fragment rows
    const int rb = ra + 8;

    for (int kt = 0; kt < 16; kt++) {
        int k0 = kt * 8;
        __syncthreads();
        // ---- stage W slice [k0..k0+8) x MO, tf32 split, cooperatively ----
        for (int i = tid * 4; i < 8 * MO; i += 1024) {
            int r = i / MO, cc = i % MO;
            float4 w = *reinterpret_cast<const float4*>(&W[(k0 + r) * MO + cc]);
            float4 hi, lo;
            hi.x = tf32r(w.x); lo.x = tf32r(w.x - hi.x);
            hi.y = tf32r(w.y); lo.y = tf32r(w.y - hi.y);
            hi.z = tf32r(w.z); lo.z = tf32r(w.z - hi.z);
            hi.w = tf32r(w.w); lo.w = tf32r(w.w - hi.w);
            *reinterpret_cast<float4*>(&Whi[r * WS + cc]) = hi;
            *reinterpret_cast<float4*>(&Wlo[r * WS + cc]) = lo;
        }
        __syncthreads();

        // ---- A fragments ----
        float a0 = Xs[ra * XS + k0 + t4];
        float a1 = Xs[rb * XS + k0 + t4];
        float a2 = Xs[ra * XS + k0 + t4 + 4];
        float a3 = Xs[rb * XS + k0 + t4 + 4];
        float ah0 = tf32r(a0), ah1 = tf32r(a1), ah2 = tf32r(a2), ah3 = tf32r(a3);
        float al0 = tf32r(a0 - ah0), al1 = tf32r(a1 - ah1);
        float al2 = tf32r(a2 - ah2), al3 = tf32r(a3 - ah3);
        unsigned uah0 = __float_as_uint(ah0), uah1 = __float_as_uint(ah1);
        unsigned uah2 = __float_as_uint(ah2), uah3 = __float_as_uint(ah3);
        unsigned ual0 = __float_as_uint(al0), ual1 = __float_as_uint(al1);
        unsigned ual2 = __float_as_uint(al2), ual3 = __float_as_uint(al3);

#pragma unroll
        for (int nt = 0; nt < NT; nt++) {
            int n0 = nt * 8;
            unsigned uwh0 = __float_as_uint(Whi[t4 * WS + n0 + gp]);
            unsigned uwh1 = __float_as_uint(Whi[(t4 + 4) * WS + n0 + gp]);
            unsigned uwl0 = __float_as_uint(Wlo[t4 * WS + n0 + gp]);
            unsigned uwl1 = __float_as_uint(Wlo[(t4 + 4) * WS + n0 + gp]);

            mma_tf32(c[nt][0], c[nt][1], c[nt][2], c[nt][3],
                     uah0, uah1, uah2, uah3, uwh0, uwh1);
            mma_tf32(c[nt][0], c[nt][1], c[nt][2], c[nt][3],
                     uah0, uah1, uah2, uah3, uwl0, uwl1);
            mma_tf32(c[nt][0], c[nt][1], c[nt][2], c[nt][3],
                     ual0, ual1, ual2, ual3, uwh0, uwh1);
        }
    }

    // ---- store H (fp32) ----
    int na = row0 + ra;
    int nb = row0 + rb;
#pragma unroll
    for (int nt = 0; nt < NT; nt++) {
        int colb = nt * 8 + 2 * t4;
        if (na < N_NODES)
            *reinterpret_cast<float2*>(&Hout[na * MO + colb]) =
                make_float2(c[nt][0], c[nt][1]);
        if (nb < N_NODES)
            *reinterpret_cast<float2*>(&Hout[nb * MO + colb]) =
                make_float2(c[nt][2], c[nt][3]);
    }

    // ---- fused coef epilogue: als/ald per row via lane-quad reduction ----
    float sA[H], dA[H], sB[H], dB[H];
#pragma unroll
    for (int h = 0; h < H; h++) { sA[h] = dA[h] = sB[h] = dB[h] = 0.f; }
#pragma unroll
    for (int nt = 0; nt < NT; nt++) {
        int c0 = nt * 8 + 2 * t4;
        float2 as2 = *reinterpret_cast<const float2*>(&a_src[c0]);
        float2 ad2 = *reinterpret_cast<const float2*>(&a_dst[c0]);
        int h = (H == 4) ? (nt >> 2) : 0;
        sA[h] = fmaf(c[nt][0], as2.x, fmaf(c[nt][1], as2.y, sA[h]));
        dA[h] = fmaf(c[nt][0], ad2.x, fmaf(c[nt][1], ad2.y, dA[h]));
        sB[h] = fmaf(c[nt][2], as2.x, fmaf(c[nt][3], as2.y, sB[h]));
        dB[h] = fmaf(c[nt][2], ad2.x, fmaf(c[nt][3], ad2.y, dB[h]));
    }
#pragma unroll
    for (int h = 0; h < H; h++) {
        sA[h] += __shfl_xor_sync(0xffffffffu, sA[h], 1);
        sA[h] += __shfl_xor_sync(0xffffffffu, sA[h], 2);
        dA[h] += __shfl_xor_sync(0xffffffffu, dA[h], 1);
        dA[h] += __shfl_xor_sync(0xffffffffu, dA[h], 2);
        sB[h] += __shfl_xor_sync(0xffffffffu, sB[h], 1);
        sB[h] += __shfl_xor_sync(0xffffffffu, sB[h], 2);
        dB[h] += __shfl_xor_sync(0xffffffffu, dB[h], 1);
        dB[h] += __shfl_xor_sync(0xffffffffu, dB[h], 2);
    }
    if (H == 4) {
        int h = t4;
        if (na < N_NODES) { als[na * 4 + h] = sA[h]; ald[na * 4 + h] = dA[h]; }
        if (nb < N_NODES) { als[nb * 4 + h] = sB[h]; ald[nb * 4 + h] = dB[h]; }
    } else {
        if (t4 == 0) {
            if (na < N_NODES) { als[na] = sA[0]; ald[na] = dA[0]; }
            if (nb < N_NODES) { als[nb] = sB[0]; ald[nb] = dB[0]; }
        }
    }
}

constexpr int SMEM_G128 = (128 * 132 + 2 * 8 * 136) * 4;   // 76288
constexpr int SMEM_G64  = (128 * 132 + 2 * 8 * 72) * 4;    // 72192

// ---------------- side stream + kernel attrs (program-load init) ----------------
struct Setup {
    cudaStream_t s;
    cudaEvent_t fork, join;
    Setup() {
        cudaStreamCreateWithFlags(&s, cudaStreamNonBlocking);
        cudaEventCreateWithFlags(&fork, cudaEventDisableTiming);
        cudaEventCreateWithFlags(&join, cudaEventDisableTiming);
        cudaFuncSetAttribute((const void*)&gemm_mma<128, 4>,
                             cudaFuncAttributeMaxDynamicSharedMemorySize, SMEM_G128);
        cudaFuncSetAttribute((const void*)&gemm_mma<64, 1>,
                             cudaFuncAttributeMaxDynamicSharedMemorySize, SMEM_G64);
    }
};
static Setup g_ss;

// ---------------- fused attention softmax + gather (H=4, F=32) ----------------
// Pass 1 accumulates softmax denominators only; pass 2 recomputes exp inline
// (identical fp32 math; avoids the p_csr round trip).
__global__ void gather4_kernel(const int* __restrict__ offsets,
                               const int* __restrict__ csr_src,
                               const float* __restrict__ als,
                               const float* __restrict__ ald,
                               const float* __restrict__ Hfeat,
                               float* __restrict__ O) {
    int warp = (blockIdx.x * blockDim.x + threadIdx.x) >> 5;
    int lane = threadIdx.x & 31;
    if (warp >= N_NODES) return;
    const int d = warp;
    const int start = offsets[d], end = offsets[d + 1];

    float4 aldv = reinterpret_cast<const float4*>(ald)[d];
    float dx = 0.f, dy = 0.f, dz = 0.f, dw = 0.f;
    for (int j = start + lane; j < end; j += 32) {
        int s = csr_src[j];
        float4 a = reinterpret_cast<const float4*>(als)[s];
        float ex = a.x + aldv.x; ex = (ex > 0.f) ? ex : SLOPE * ex;
        float ey = a.y + aldv.y; ey = (ey > 0.f) ? ey : SLOPE * ey;
        float ez = a.z + aldv.z; ez = (ez > 0.f) ? ez : SLOPE * ez;
        float ew = a.w + aldv.w; ew = (ew > 0.f) ? ew : SLOPE * ew;
        dx += __expf(ex); dy += __expf(ey); dz += __expf(ez); dw += __expf(ew);
    }
#pragma unroll
    for (int o = 16; o > 0; o >>= 1) {
        dx += __shfl_xor_sync(0xffffffffu, dx, o);
        dy += __shfl_xor_sync(0xffffffffu, dy, o);
        dz += __shfl_xor_sync(0xffffffffu, dz, o);
        dw += __shfl_xor_sync(0xffffffffu, dw, o);
    }
    const int h = lane >> 3;                       // head for this lane's float4
    float den = (h == 0) ? dx : (h == 1) ? dy : (h == 2) ? dz : dw;
    float invd = __fdividef(1.f, den);
    float aldh = (h == 0) ? aldv.x : (h == 1) ? aldv.y : (h == 2) ? aldv.z : aldv.w;

    float4 acc = make_float4(0.f, 0.f, 0.f, 0.f);
#pragma unroll 4
    for (int j = start; j < end; j++) {
        int s = csr_src[j];                        // broadcast
        float e = als[s * 4 + h] + aldh;           // group-of-8 broadcast sector
        e = (e > 0.f) ? e : SLOPE * e;
        float alpha = __expf(e) * invd;
        float4 hv = reinterpret_cast<const float4*>(Hfeat)[s * 32 + lane];
        acc.x = fmaf(hv.x, alpha, acc.x);
        acc.y = fmaf(hv.y, alpha, acc.y);
        acc.z = fmaf(hv.z, alpha, acc.z);
        acc.w = fmaf(hv.w, alpha, acc.w);
    }
    reinterpret_cast<float4*>(O)[d * 32 + lane] = acc;
}

// ---------------- fused gather (H=1,F=64) + bias + log_softmax ----------------
__global__ void gather1_final(const int* __restrict__ offsets,
                              const int* __restrict__ csr_src,
                              const float* __restrict__ als,
                              const float* __restrict__ ald,
                              const float* __restrict__ Hfeat,
                              const float* __restrict__ b3,
                              float* __restrict__ out) {
    int warp = (blockIdx.x * blockDim.x + threadIdx.x) >> 5;
    int lane = threadIdx.x & 31;
    if (warp >= N_NODES) return;
    const int d = warp;
    const int start = offsets[d], end = offsets[d + 1];

    float aldd = ald[d];
    float den = 0.f;
    for (int j = start + lane; j < end; j += 32) {
        int s = csr_src[j];
        float e = als[s] + aldd;
        e = (e > 0.f) ? e : SLOPE * e;
        den += __expf(e);
    }
#pragma unroll
    for (int o = 16; o > 0; o >>= 1) den += __shfl_xor_sync(0xffffffffu, den, o);
    float invd = __fdividef(1.f, den);

    float2 acc = make_float2(0.f, 0.f);
#pragma unroll 4
    for (int j = start; j < end; j++) {
        int s = csr_src[j];
        float e = als[s] + aldd;                   // broadcast
        e = (e > 0.f) ? e : SLOPE * e;
        float alpha = __expf(e) * invd;
        float2 hv = reinterpret_cast<const float2*>(Hfeat)[s * 32 + lane];
        acc.x = fmaf(hv.x, alpha, acc.x);
        acc.y = fmaf(hv.y, alpha, acc.y);
    }

    // log_softmax over the 64 classes held pairwise across the warp
    float2 b = reinterpret_cast<const float2*>(b3)[lane];
    float v0 = acc.x + b.x;
    float v1 = acc.y + b.y;
    float mx = fmaxf(v0, v1);
#pragma unroll
    for (int o = 16; o > 0; o >>= 1) mx = fmaxf(mx, __shfl_xor_sync(0xffffffffu, mx, o));
    float se = expf(v0 - mx) + expf(v1 - mx);
#pragma unroll
    for (int o = 16; o > 0; o >>= 1) se += __shfl_xor_sync(0xffffffffu, se, o);
    float lse = mx + logf(se);
    reinterpret_cast<float2*>(out)[d * 32 + lane] = make_float2(v0 - lse, v1 - lse);
}

// ---------------- launcher ----------------
extern "C" void kernel_launch(void* const* d_in, const int* in_sizes, int n_in,
                              void* d_out, int out_size) {
    const float* x   = (const float*)d_in[0];
    const int*   ei  = (const int*)  d_in[1];
    const float* w1  = (const float*)d_in[2];
    const float* as1 = (const float*)d_in[3];
    const float* ad1 = (const float*)d_in[4];
    const float* b1  = (const float*)d_in[5];
    const float* w2  = (const float*)d_in[6];
    const float* as2 = (const float*)d_in[7];
    const float* ad2 = (const float*)d_in[8];
    const float* b2  = (const float*)d_in[9];
    const float* w3  = (const float*)d_in[10];
    const float* as3 = (const float*)d_in[11];
    const float* ad3 = (const float*)d_in[12];
    const float* b3  = (const float*)d_in[13];
    float* out = (float*)d_out;

    float *hbuf, *obuf, *als, *ald;
    int *cnt, *off, *cur, *csrc;
    cudaGetSymbolAddress((void**)&hbuf, g_h);
    cudaGetSymbolAddress((void**)&obuf, g_o);
    cudaGetSymbolAddress((void**)&als,  g_als);
    cudaGetSymbolAddress((void**)&ald,  g_ald);
    cudaGetSymbolAddress((void**)&cnt,  g_cnt);
    cudaGetSymbolAddress((void**)&off,  g_off);
    cudaGetSymbolAddress((void**)&cur,  g_cur);
    cudaGetSymbolAddress((void**)&csrc, g_csrc);

    auto cdiv = [](long long a, long long b) { return (int)((a + b - 1) / b); };

    const int gatherGrid = cdiv((long long)N_NODES * 32, 256);
    const int gemmGrid = cdiv(N_NODES, 128);   // 391

    // ---- fork: CSR build on side stream, concurrent with layer-1 GEMM ----
    cudaEventRecord(g_ss.fork, 0);
    cudaStreamWaitEvent(g_ss.s, g_ss.fork, 0);
    zero_int_kernel<<<cdiv(N_NODES, 256), 256, 0, g_ss.s>>>(cnt, N_NODES);
    hist_kernel<<<cdiv(E_TOT, 256), 256, 0, g_ss.s>>>(ei, cnt);
    scan_kernel<<<1, 1024, 0, g_ss.s>>>(cnt, off, cur);
    scatter_kernel<<<cdiv(E_TOT, 256), 256, 0, g_ss.s>>>(ei, cur, csrc);
    cudaEventRecord(g_ss.join, g_ss.s);

    // ---- layer 1 (main stream, overlaps CSR build) ----
    gemm_mma<128, 4><<<gemmGrid, 256, SMEM_G128>>>(x, w1, nullptr, as1, ad1,
                                                   hbuf, als, ald);
    cudaStreamWaitEvent(0, g_ss.join, 0);          // join before gather
    gather4_kernel<<<gatherGrid, 256>>>(off, csrc, als, ald, hbuf, obuf);

    // ---- layer 2 ----
    gemm_mma<128, 4><<<gemmGrid, 256, SMEM_G128>>>(obuf, w2, b1, as2, ad2,
                                                   hbuf, als, ald);
    gather4_kernel<<<gatherGrid, 256>>>(off, csrc, als, ald, hbuf, obuf);

    // ---- layer 3 (gather fused with bias + log_softmax) ----
    gemm_mma<64, 1><<<gemmGrid, 256, SMEM_G64>>>(obuf, w3, b2, as3, ad3,
                                                 hbuf, als, ald);
    gather1_final<<<gatherGrid, 256>>>(off, csrc, als, ald, hbuf, b3, out);
}

// round 11
// speedup vs baseline: 1.0805x; 1.0805x over previous
#include <cuda_runtime.h>
#include <math.h>

#define N_NODES 50000
#define E_EDGES 800000
#define E_TOT   (E_EDGES + N_NODES)   // 850000 with self loops
#define F_IN    128
#define SLOPE   0.2f

// ---------------- scratch (static __device__ — no allocation) ----------------
__device__ float g_h[N_NODES * 128];        // transformed features (fp32)
__device__ float g_o[N_NODES * 128];        // aggregated output
__device__ float g_als[N_NODES * 4];
__device__ float g_ald[N_NODES * 4];
__device__ int   g_cnt[N_NODES];
__device__ int   g_off[N_NODES + 1];
__device__ int   g_cur[N_NODES];
__device__ int   g_csrc[E_TOT];

// ---------------- CSR build ----------------
__global__ void zero_int_kernel(int* p, int n) {
    int i = blockIdx.x * blockDim.x + threadIdx.x;
    if (i < n) p[i] = 0;
}

__global__ void hist_kernel(const int* __restrict__ ei, int* __restrict__ cnt) {
    int e = blockIdx.x * blockDim.x + threadIdx.x;
    if (e >= E_TOT) return;
    int d = (e < E_EDGES) ? ei[E_EDGES + e] : (e - E_EDGES);
    atomicAdd(&cnt[d], 1);
}

__global__ void scan_kernel(const int* __restrict__ cnt,
                            int* __restrict__ offsets,
                            int* __restrict__ cursor) {
    __shared__ int part[1024];
    const int T = 1024;
    const int C = (N_NODES + T - 1) / T;   // 49
    int t = threadIdx.x;
    int lo = t * C;
    int hi = lo + C; if (hi > N_NODES) hi = N_NODES;
    int s = 0;
    for (int i = lo; i < hi; i++) s += cnt[i];
    part[t] = s;
    __syncthreads();
    for (int off = 1; off < T; off <<= 1) {
        int v = (t >= off) ? part[t - off] : 0;
        __syncthreads();
        part[t] += v;
        __syncthreads();
    }
    int run = (t > 0) ? part[t - 1] : 0;   // exclusive base
    for (int i = lo; i < hi; i++) {
        offsets[i] = run;
        cursor[i]  = run;
        run += cnt[i];
    }
    if (t == 0) offsets[N_NODES] = E_TOT;
}

__global__ void scatter_kernel(const int* __restrict__ ei,
                               int* __restrict__ cursor,
                               int* __restrict__ csr_src) {
    int e = blockIdx.x * blockDim.x + threadIdx.x;
    if (e >= E_TOT) return;
    int s, d;
    if (e < E_EDGES) { s = ei[e]; d = ei[E_EDGES + e]; }
    else             { s = d = e - E_EDGES; }
    int pos = atomicAdd(&cursor[d], 1);
    csr_src[pos] = s;
}

// ---------------- tf32 helpers ----------------
__device__ __forceinline__ float tf32r(float x) {
    float r;
    asm("cvt.rna.tf32.f32 %0, %1;" : "=f"(r) : "f"(x));
    return r;
}

__device__ __forceinline__ void mma_tf32(float& c0, float& c1, float& c2, float& c3,
                                         unsigned a0, unsigned a1, unsigned a2, unsigned a3,
                                         unsigned b0, unsigned b1) {
    asm volatile(
        "mma.sync.aligned.m16n8k8.row.col.f32.tf32.tf32.f32 "
        "{%0,%1,%2,%3}, {%4,%5,%6,%7}, {%8,%9}, {%0,%1,%2,%3};"
        : "+f"(c0), "+f"(c1), "+f"(c2), "+f"(c3)
        : "r"(a0), "r"(a1), "r"(a2), "r"(a3), "r"(b0), "r"(b1));
}

// ---------------- GEMM (tf32x3) + fused attention-coef epilogue ----------------
template<int MO, int H>
__global__ void __launch_bounds__(256)
gemm_mma(const float* __restrict__ X,
         const float* __restrict__ W,
         const float* __restrict__ bias,
         const float* __restrict__ a_src,
         const float* __restrict__ a_dst,
         float* __restrict__ Hout,
         float* __restrict__ als,
         float* __restrict__ ald) {
    constexpr int XS = 132;                      // X row stride
    constexpr int WS = MO + 8;                   // WS % 32 == 8
    constexpr int NT = MO / 8;                   // n-tiles per warp

    extern __shared__ float smem_f[];
    float* Xs  = smem_f;                         // 128 * XS
    float* Whi = Xs + 128 * XS;                  // 8 * WS
    float* Wlo = Whi + 8 * WS;                   // 8 * WS

    const int tid  = threadIdx.x;
    const int wid  = tid >> 5;
    const int lane = tid & 31;
    const int gp   = lane >> 2;                  // group 0..7
    const int t4   = lane & 3;                   // 0..3
    const int row0 = blockIdx.x * 128;

    // ---- stage X tile (with fused relu(x+bias) of previous layer) ----
#pragma unroll
    for (int it = 0; it < 16; it++) {
        int idx = tid + it * 256;                // 0..4095
        int r  = idx >> 5;
        int k4 = idx & 31;
        int n  = row0 + r;
        float4 v = make_float4(0.f, 0.f, 0.f, 0.f);
        if (n < N_NODES) {
            v = reinterpret_cast<const float4*>(X)[n * 32 + k4];
            if (bias) {
                float4 b = reinterpret_cast<const float4*>(bias)[k4];
                v.x = fmaxf(v.x + b.x, 0.f);
                v.y = fmaxf(v.y + b.y, 0.f);
                v.z = fmaxf(v.z + b.z, 0.f);
                v.w = fmaxf(v.w + b.w, 0.f);
            }
        }
        *reinterpret_cast<float4*>(&Xs[r * XS + 4 * k4]) = v;
    }

    float c[NT][4];
#pragma unroll
    for (int nt = 0; nt < NT; nt++)
#pragma unroll
        for (int j = 0; j < 4; j++) c[nt][j] = 0.f;

    const int ra = wid * 16 + gp;                // fragment rows
    const int rb = ra + 8;

    for (int kt = 0; kt < 16; kt++) {
        int k0 = kt * 8;
        __syncthreads();
        // ---- stage W slice [k0..k0+8) x MO, tf32 split, cooperatively ----
        for (int i = tid * 4; i < 8 * MO; i += 1024) {
            int r = i / MO, cc = i % MO;
            float4 w = *reinterpret_cast<const float4*>(&W[(k0 + r) * MO + cc]);
            float4 hi, lo;
            hi.x = tf32r(w.x); lo.x = tf32r(w.x - hi.x);
            hi.y = tf32r(w.y); lo.y = tf32r(w.y - hi.y);
            hi.z = tf32r(w.z); lo.z = tf32r(w.z - hi.z);
            hi.w = tf32r(w.w); lo.w = tf32r(w.w - hi.w);
            *reinterpret_cast<float4*>(&Whi[r * WS + cc]) = hi;
            *reinterpret_cast<float4*>(&Wlo[r * WS + cc]) = lo;
        }
        __syncthreads();

        // ---- A fragments ----
        float a0 = Xs[ra * XS + k0 + t4];
        float a1 = Xs[rb * XS + k0 + t4];
        float a2 = Xs[ra * XS + k0 + t4 + 4];
        float a3 = Xs[rb * XS + k0 + t4 + 4];
        float ah0 = tf32r(a0), ah1 = tf32r(a1), ah2 = tf32r(a2), ah3 = tf32r(a3);
        float al0 = tf32r(a0 - ah0), al1 = tf32r(a1 - ah1);
        float al2 = tf32r(a2 - ah2), al3 = tf32r(a3 - ah3);
        unsigned uah0 = __float_as_uint(ah0), uah1 = __float_as_uint(ah1);
        unsigned uah2 = __float_as_uint(ah2), uah3 = __float_as_uint(ah3);
        unsigned ual0 = __float_as_uint(al0), ual1 = __float_as_uint(al1);
        unsigned ual2 = __float_as_uint(al2), ual3 = __float_as_uint(al3);

#pragma unroll
        for (int nt = 0; nt < NT; nt++) {
            int n0 = nt * 8;
            unsigned uwh0 = __float_as_uint(Whi[t4 * WS + n0 + gp]);
            unsigned uwh1 = __float_as_uint(Whi[(t4 + 4) * WS + n0 + gp]);
            unsigned uwl0 = __float_as_uint(Wlo[t4 * WS + n0 + gp]);
            unsigned uwl1 = __float_as_uint(Wlo[(t4 + 4) * WS + n0 + gp]);

            mma_tf32(c[nt][0], c[nt][1], c[nt][2], c[nt][3],
                     uah0, uah1, uah2, uah3, uwh0, uwh1);
            mma_tf32(c[nt][0], c[nt][1], c[nt][2], c[nt][3],
                     uah0, uah1, uah2, uah3, uwl0, uwl1);
            mma_tf32(c[nt][0], c[nt][1], c[nt][2], c[nt][3],
                     ual0, ual1, ual2, ual3, uwh0, uwh1);
        }
    }

    // ---- store H (fp32) ----
    int na = row0 + ra;
    int nb = row0 + rb;
#pragma unroll
    for (int nt = 0; nt < NT; nt++) {
        int colb = nt * 8 + 2 * t4;
        if (na < N_NODES)
            *reinterpret_cast<float2*>(&Hout[na * MO + colb]) =
                make_float2(c[nt][0], c[nt][1]);
        if (nb < N_NODES)
            *reinterpret_cast<float2*>(&Hout[nb * MO + colb]) =
                make_float2(c[nt][2], c[nt][3]);
    }

    // ---- fused coef epilogue: als/ald per row via lane-quad reduction ----
    float sA[H], dA[H], sB[H], dB[H];
#pragma unroll
    for (int h = 0; h < H; h++) { sA[h] = dA[h] = sB[h] = dB[h] = 0.f; }
#pragma unroll
    for (int nt = 0; nt < NT; nt++) {
        int c0 = nt * 8 + 2 * t4;
        float2 as2 = *reinterpret_cast<const float2*>(&a_src[c0]);
        float2 ad2 = *reinterpret_cast<const float2*>(&a_dst[c0]);
        int h = (H == 4) ? (nt >> 2) : 0;
        sA[h] = fmaf(c[nt][0], as2.x, fmaf(c[nt][1], as2.y, sA[h]));
        dA[h] = fmaf(c[nt][0], ad2.x, fmaf(c[nt][1], ad2.y, dA[h]));
        sB[h] = fmaf(c[nt][2], as2.x, fmaf(c[nt][3], as2.y, sB[h]));
        dB[h] = fmaf(c[nt][2], ad2.x, fmaf(c[nt][3], ad2.y, dB[h]));
    }
#pragma unroll
    for (int h = 0; h < H; h++) {
        sA[h] += __shfl_xor_sync(0xffffffffu, sA[h], 1);
        sA[h] += __shfl_xor_sync(0xffffffffu, sA[h], 2);
        dA[h] += __shfl_xor_sync(0xffffffffu, dA[h], 1);
        dA[h] += __shfl_xor_sync(0xffffffffu, dA[h], 2);
        sB[h] += __shfl_xor_sync(0xffffffffu, sB[h], 1);
        sB[h] += __shfl_xor_sync(0xffffffffu, sB[h], 2);
        dB[h] += __shfl_xor_sync(0xffffffffu, dB[h], 1);
        dB[h] += __shfl_xor_sync(0xffffffffu, dB[h], 2);
    }
    if (H == 4) {
        int h = t4;
        if (na < N_NODES) { als[na * 4 + h] = sA[h]; ald[na * 4 + h] = dA[h]; }
        if (nb < N_NODES) { als[nb * 4 + h] = sB[h]; ald[nb * 4 + h] = dB[h]; }
    } else {
        if (t4 == 0) {
            if (na < N_NODES) { als[na] = sA[0]; ald[na] = dA[0]; }
            if (nb < N_NODES) { als[nb] = sB[0]; ald[nb] = dB[0]; }
        }
    }
}

constexpr int SMEM_G128 = (128 * 132 + 2 * 8 * 136) * 4;   // 76288
constexpr int SMEM_G64  = (128 * 132 + 2 * 8 * 72) * 4;    // 72192

// ---------------- side stream + kernel attrs (program-load init) ----------------
struct Setup {
    cudaStream_t s;
    cudaEvent_t fork, join;
    Setup() {
        cudaStreamCreateWithFlags(&s, cudaStreamNonBlocking);
        cudaEventCreateWithFlags(&fork, cudaEventDisableTiming);
        cudaEventCreateWithFlags(&join, cudaEventDisableTiming);
        cudaFuncSetAttribute((const void*)&gemm_mma<128, 4>,
                             cudaFuncAttributeMaxDynamicSharedMemorySize, SMEM_G128);
        cudaFuncSetAttribute((const void*)&gemm_mma<64, 1>,
                             cudaFuncAttributeMaxDynamicSharedMemorySize, SMEM_G64);
    }
};
static Setup g_ss;

// ---------------- single-pass softmax gather (H=4, F=32) ----------------
// out[d] = (sum_j p_j * h[src_j]) / (sum_j p_j); p computed once per edge.
// Within each group of 8 lanes (one head) every lane computes the same p,
// so den is replicated — no reduction needed.
__global__ void gather4_kernel(const int* __restrict__ offsets,
                               const int* __restrict__ csr_src,
                               const float* __restrict__ als,
                               const float* __restrict__ ald,
                               const float* __restrict__ Hfeat,
                               float* __restrict__ O) {
    int warp = (blockIdx.x * blockDim.x + threadIdx.x) >> 5;
    int lane = threadIdx.x & 31;
    if (warp >= N_NODES) return;
    const int d = warp;
    const int start = offsets[d], end = offsets[d + 1];
    const int h = lane >> 3;                       // head for this lane's float4

    float4 aldv = reinterpret_cast<const float4*>(ald)[d];
    float aldh = (h == 0) ? aldv.x : (h == 1) ? aldv.y : (h == 2) ? aldv.z : aldv.w;

    float den = 0.f;
    float4 acc = make_float4(0.f, 0.f, 0.f, 0.f);
#pragma unroll 4
    for (int j = start; j < end; j++) {
        int s = csr_src[j];                        // warp-uniform broadcast
        float e = als[s * 4 + h] + aldh;           // 4 distinct addrs per warp
        e = (e > 0.f) ? e : SLOPE * e;
        float p = __expf(e);
        den += p;
        float4 hv = reinterpret_cast<const float4*>(Hfeat)[s * 32 + lane];
        acc.x = fmaf(hv.x, p, acc.x);
        acc.y = fmaf(hv.y, p, acc.y);
        acc.z = fmaf(hv.z, p, acc.z);
        acc.w = fmaf(hv.w, p, acc.w);
    }
    float invd = __fdividef(1.f, den);
    acc.x *= invd; acc.y *= invd; acc.z *= invd; acc.w *= invd;
    reinterpret_cast<float4*>(O)[d * 32 + lane] = acc;
}

// ---------------- single-pass gather (H=1,F=64) + bias + log_softmax ----------------
__global__ void gather1_final(const int* __restrict__ offsets,
                              const int* __restrict__ csr_src,
                              const float* __restrict__ als,
                              const float* __restrict__ ald,
                              const float* __restrict__ Hfeat,
                              const float* __restrict__ b3,
                              float* __restrict__ out) {
    int warp = (blockIdx.x * blockDim.x + threadIdx.x) >> 5;
    int lane = threadIdx.x & 31;
    if (warp >= N_NODES) return;
    const int d = warp;
    const int start = offsets[d], end = offsets[d + 1];

    float aldd = ald[d];
    float den = 0.f;
    float2 acc = make_float2(0.f, 0.f);
#pragma unroll 4
    for (int j = start; j < end; j++) {
        int s = csr_src[j];                        // warp-uniform broadcast
        float e = als[s] + aldd;                   // single addr, broadcast
        e = (e > 0.f) ? e : SLOPE * e;
        float p = __expf(e);
        den += p;
        float2 hv = reinterpret_cast<const float2*>(Hfeat)[s * 32 + lane];
        acc.x = fmaf(hv.x, p, acc.x);
        acc.y = fmaf(hv.y, p, acc.y);
    }
    float invd = __fdividef(1.f, den);

    // log_softmax over the 64 classes held pairwise across the warp
    float2 b = reinterpret_cast<const float2*>(b3)[lane];
    float v0 = acc.x * invd + b.x;
    float v1 = acc.y * invd + b.y;
    float mx = fmaxf(v0, v1);
#pragma unroll
    for (int o = 16; o > 0; o >>= 1) mx = fmaxf(mx, __shfl_xor_sync(0xffffffffu, mx, o));
    float se = expf(v0 - mx) + expf(v1 - mx);
#pragma unroll
    for (int o = 16; o > 0; o >>= 1) se += __shfl_xor_sync(0xffffffffu, se, o);
    float lse = mx + logf(se);
    reinterpret_cast<float2*>(out)[d * 32 + lane] = make_float2(v0 - lse, v1 - lse);
}

// ---------------- launcher ----------------
extern "C" void kernel_launch(void* const* d_in, const int* in_sizes, int n_in,
                              void* d_out, int out_size) {
    const float* x   = (const float*)d_in[0];
    const int*   ei  = (const int*)  d_in[1];
    const float* w1  = (const float*)d_in[2];
    const float* as1 = (const float*)d_in[3];
    const float* ad1 = (const float*)d_in[4];
    const float* b1  = (const float*)d_in[5];
    const float* w2  = (const float*)d_in[6];
    const float* as2 = (const float*)d_in[7];
    const float* ad2 = (const float*)d_in[8];
    const float* b2  = (const float*)d_in[9];
    const float* w3  = (const float*)d_in[10];
    const float* as3 = (const float*)d_in[11];
    const float* ad3 = (const float*)d_in[12];
    const float* b3  = (const float*)d_in[13];
    float* out = (float*)d_out;

    float *hbuf, *obuf, *als, *ald;
    int *cnt, *off, *cur, *csrc;
    cudaGetSymbolAddress((void**)&hbuf, g_h);
    cudaGetSymbolAddress((void**)&obuf, g_o);
    cudaGetSymbolAddress((void**)&als,  g_als);
    cudaGetSymbolAddress((void**)&ald,  g_ald);
    cudaGetSymbolAddress((void**)&cnt,  g_cnt);
    cudaGetSymbolAddress((void**)&off,  g_off);
    cudaGetSymbolAddress((void**)&cur,  g_cur);
    cudaGetSymbolAddress((void**)&csrc, g_csrc);

    auto cdiv = [](long long a, long long b) { return (int)((a + b - 1) / b); };

    const int gatherGrid = cdiv((long long)N_NODES * 32, 256);
    const int gemmGrid = cdiv(N_NODES, 128);   // 391

    // ---- fork: CSR build on side stream, concurrent with layer-1 GEMM ----
    cudaEventRecord(g_ss.fork, 0);
    cudaStreamWaitEvent(g_ss.s, g_ss.fork, 0);
    zero_int_kernel<<<cdiv(N_NODES, 256), 256, 0, g_ss.s>>>(cnt, N_NODES);
    hist_kernel<<<cdiv(E_TOT, 256), 256, 0, g_ss.s>>>(ei, cnt);
    scan_kernel<<<1, 1024, 0, g_ss.s>>>(cnt, off, cur);
    scatter_kernel<<<cdiv(E_TOT, 256), 256, 0, g_ss.s>>>(ei, cur, csrc);
    cudaEventRecord(g_ss.join, g_ss.s);

    // ---- layer 1 (main stream, overlaps CSR build) ----
    gemm_mma<128, 4><<<gemmGrid, 256, SMEM_G128>>>(x, w1, nullptr, as1, ad1,
                                                   hbuf, als, ald);
    cudaStreamWaitEvent(0, g_ss.join, 0);          // join before gather
    gather4_kernel<<<gatherGrid, 256>>>(off, csrc, als, ald, hbuf, obuf);

    // ---- layer 2 ----
    gemm_mma<128, 4><<<gemmGrid, 256, SMEM_G128>>>(obuf, w2, b1, as2, ad2,
                                                   hbuf, als, ald);
    gather4_kernel<<<gatherGrid, 256>>>(off, csrc, als, ald, hbuf, obuf);

    // ---- layer 3 (gather fused with bias + log_softmax) ----
    gemm_mma<64, 1><<<gemmGrid, 256, SMEM_G64>>>(obuf, w3, b2, as3, ad3,
                                                 hbuf, als, ald);
    gather1_final<<<gatherGrid, 256>>>(off, csrc, als, ald, hbuf, b3, out);
}